// round 15
// baseline (speedup 1.0000x reference)
#include <cuda_runtime.h>
#include <cuda_bf16.h>
#include <math.h>

#define M_ROWS   65536
#define D_DIM    64
#define K_CODES  4096
#define KS       72                       // padded K stride (bf16), 64 used
#define NSTEP    4                        // k16 steps (4*16 = 64)
#define MT       64                       // rows per tile
#define MTILES   (M_ROWS / MT)            // 1024
#define GRID_A   512                      // persistent: each CTA does 2 tiles, single wave
#define CTA_THREADS 128
#define NCB16    (K_CODES / 16)           // 256 16-code blocks
#define A_BYTES  (MT * KS * 2)            // 9216
#define A_UNITS  (A_BYTES / 16)           // 576
#define RES_BYTES (3 * 128 * 4)           // top-3 staging [2 colgroups][64 rows]
#define SMEM_DYN (A_BYTES + RES_BYTES)

// ---- global scratch (static __device__; no runtime allocs) ----
__device__ __align__(16) unsigned char g_A[(size_t)M_ROWS * KS * 2];          // ~9.4 MB
__device__ __align__(16) unsigned char g_Bf[(size_t)NCB16 * NSTEP * 32 * 16]; // 512 KB frag-packed
__device__ float4 g_Cfq[NCB16 * 4];                                           // -c seeds per (block, quad)
__device__ float g_c[K_CODES];                                                // 0.5*||e||^2
__device__ __align__(16) float4 g_top4[M_ROWS];                               // per-row top-3 packed
__device__ float g_partials[256];

#define NEG_INF (-3.402823466e38f)

// ======================= helpers (compute_103-safe) =======================
__device__ __forceinline__ unsigned smem_u32(const void* p) {
    unsigned a;
    asm("{ .reg .u64 t; cvta.to.shared.u64 t, %1; cvt.u32.u64 %0, t; }" : "=r"(a) : "l"(p));
    return a;
}
__device__ __forceinline__ unsigned pack_bf16x2(float lo, float hi) {
    unsigned r;
    asm("cvt.rn.bf16x2.f32 %0, %1, %2;" : "=r"(r) : "f"(hi), "f"(lo));
    return r;  // low 16 bits (first in memory) = lo
}
__device__ __forceinline__ void cp_async16(unsigned saddr, const void* gaddr) {
    asm volatile("cp.async.cg.shared.global [%0], [%1], 16;" :: "r"(saddr), "l"(gaddr) : "memory");
}
__device__ __forceinline__ void cp_commit() {
    asm volatile("cp.async.commit_group;" ::: "memory");
}
template <int N>
__device__ __forceinline__ void cp_wait() {
    asm volatile("cp.async.wait_group %0;" :: "n"(N) : "memory");
}
__device__ __forceinline__ void ldsm_x4(unsigned* r, unsigned addr) {
    asm volatile("ldmatrix.sync.aligned.m8n8.x4.shared.b16 {%0,%1,%2,%3}, [%4];"
                 : "=r"(r[0]), "=r"(r[1]), "=r"(r[2]), "=r"(r[3]) : "r"(addr));
}
__device__ __forceinline__ void mma16816(float* c, const unsigned* a, const unsigned* b) {
    asm volatile(
        "mma.sync.aligned.m16n8k16.row.col.f32.bf16.bf16.f32 "
        "{%0,%1,%2,%3}, {%4,%5,%6,%7}, {%8,%9}, {%0,%1,%2,%3};"
        : "+f"(c[0]), "+f"(c[1]), "+f"(c[2]), "+f"(c[3])
        : "r"(a[0]), "r"(a[1]), "r"(a[2]), "r"(a[3]), "r"(b[0]), "r"(b[1]));
}
__device__ __forceinline__ void ins3f(float* v, float nv) {
    if (nv > v[0])      { v[2] = v[1]; v[1] = v[0]; v[0] = nv; }
    else if (nv > v[1]) { v[2] = v[1]; v[1] = nv; }
    else if (nv > v[2]) { v[2] = nv; }
}
__device__ __forceinline__ void merge3f_shfl(float* v, int off) {
    float ov[3];
    #pragma unroll
    for (int j = 0; j < 3; j++) ov[j] = __shfl_xor_sync(0xffffffffu, v[j], off);
    #pragma unroll
    for (int j = 0; j < 3; j++) ins3f(v, ov[j]);
}

// ===================== prep kernels =====================
__global__ void vq_prep_c(const float* __restrict__ cb) {
    int k    = blockIdx.x * 8 + (threadIdx.x >> 5);
    int lane = threadIdx.x & 31;
    float2 v = reinterpret_cast<const float2*>(cb + (size_t)k * D_DIM)[lane];
    float s  = v.x * v.x + v.y * v.y;
    #pragma unroll
    for (int o = 16; o > 0; o >>= 1) s += __shfl_down_sync(0xffffffffu, s, o);
    if (lane == 0) g_c[k] = 0.5f * s;
}

// -c seeds: g_Cfq[gb*4+q] = {-c[gb*16+q*2], -c[+1], -c[gb*16+8+q*2], -c[+1]}
__global__ void vq_prep_Cf() {
    int t  = threadIdx.x;           // 1024 threads
    int gb = t >> 2, q = t & 3;
    int b  = gb * 16 + q * 2;
    g_Cfq[t] = make_float4(-g_c[b], -g_c[b + 1], -g_c[b + 8], -g_c[b + 9]);
}

// A row m: [zh(0:64) | 0 pad to 72]
__global__ void vq_prep_A(const float* __restrict__ z) {
    int m = blockIdx.x * 8 + (threadIdx.x >> 5);
    int l = threadIdx.x & 31;
    float2 x = reinterpret_cast<const float2*>(z + (size_t)m * D_DIM)[l];
    unsigned H = pack_bf16x2(x.x, x.y);
    unsigned* row = reinterpret_cast<unsigned*>(g_A) + (size_t)m * (KS / 2);
    row[l] = H;
    if (l < 4) row[32 + l] = 0u;
}

// fragment-packed B: word idx = ((cb16*4 + s)*32 + lane)*4 + q
__global__ void vq_prep_Bf(const float* __restrict__ cb) {
    int idx = blockIdx.x * 256 + threadIdx.x;     // 131072 words
    int q    = idx & 3;
    int t    = idx >> 2;
    int lane = t & 31;  t >>= 5;
    int s    = t % NSTEP;
    int cb16 = t / NSTEP;
    int n = cb16 * 16 + ((q >> 1) ? 8 : 0) + (lane >> 2);
    int k = s * 16 + ((q & 1) ? 8 : 0) + (lane & 3) * 2;
    float v0 = cb[n * D_DIM + k];
    float v1 = cb[n * D_DIM + k + 1];
    reinterpret_cast<unsigned*>(g_Bf)[idx] = pack_bf16x2(v0, v1);
}

// ===================== kernel A: persistent GEMM + argmax =====================
#define ACC(ra, p) (&acc[((ra) * 2 + (p)) * 4])

__global__ void __launch_bounds__(CTA_THREADS, 4)
vq_mma_kernel() {
    extern __shared__ unsigned char smem_raw[];

    const unsigned uA = smem_u32(smem_raw);
    float* s_v0 = reinterpret_cast<float*>(smem_raw + A_BYTES);   // [2][64]
    float* s_v1 = s_v0 + 128;
    float* s_v2 = s_v1 + 128;

    const int tid  = threadIdx.x;
    const int l    = tid & 31;
    const int rg   = (tid >> 5) >> 1;     // rows rg*32..+31
    const int wc   = (tid >> 5) & 1;      // cb16 blocks wc*128..+127

    const unsigned lane_q = (unsigned)(l & 3);
    const uint4* bf0 = reinterpret_cast<const uint4*>(g_Bf)
                     + (size_t)(wc * 128) * NSTEP * 32 + l;
    const unsigned a_lane = ((unsigned)(rg * 32 + (l & 15)) * KS
                             + (unsigned)(l >> 4) * 8) * 2;

    // stage first A tile
    {
        const unsigned char* gA = g_A + (size_t)blockIdx.x * A_BYTES;
        for (int u = tid; u < A_UNITS; u += CTA_THREADS) cp_async16(uA + u * 16, gA + u * 16);
        cp_commit();
    }

    for (int tile = blockIdx.x; tile < MTILES; tile += GRID_A) {
        cp_wait<0>();
        __syncthreads();

        unsigned aA[2][NSTEP][4];
        #pragma unroll
        for (int ra = 0; ra < 2; ra++)
            #pragma unroll
            for (int s = 0; s < NSTEP; s++)
                ldsm_x4(aA[ra][s], uA + a_lane + (unsigned)ra * (16u * KS * 2)
                                       + (unsigned)s * 32);
        __syncthreads();

        // prefetch next tile's A (overlaps entire block stream)
        if (tile + GRID_A < MTILES) {
            const unsigned char* gA = g_A + (size_t)(tile + GRID_A) * A_BYTES;
            for (int u = tid; u < A_UNITS; u += CTA_THREADS) cp_async16(uA + u * 16, gA + u * 16);
            cp_commit();
        }

        float cb_[4], cs_[4];
        #pragma unroll
        for (int i = 0; i < 4; i++) { cb_[i] = NEG_INF; cs_[i] = NEG_INF; }

        #pragma unroll 2
        for (int blk = 0; blk < 128; blk++) {
            const int gb = wc * 128 + blk;
            const uint4* bp = bf0 + (size_t)blk * (NSTEP * 32);

            const float4 cf = __ldg(&g_Cfq[gb * 4 + (int)lane_q]);
            uint4 bv[NSTEP];
            #pragma unroll
            for (int s = 0; s < NSTEP; s++) bv[s] = __ldg(bp + s * 32);

            float acc[16];
            #pragma unroll
            for (int ra = 0; ra < 2; ra++) {
                float* P0 = ACC(ra, 0);
                float* P1 = ACC(ra, 1);
                P0[0] = cf.x; P0[1] = cf.y; P0[2] = cf.x; P0[3] = cf.y;
                P1[0] = cf.z; P1[1] = cf.w; P1[2] = cf.z; P1[3] = cf.w;
            }
            #pragma unroll
            for (int s = 0; s < NSTEP; s++) {
                const unsigned* b = reinterpret_cast<const unsigned*>(&bv[s]);
                mma16816(ACC(0,0), aA[0][s], b); mma16816(ACC(0,1), aA[0][s], b + 2);
                mma16816(ACC(1,0), aA[1][s], b); mma16816(ACC(1,1), aA[1][s], b + 2);
            }

            // fold: pair-max {c0,c0+1}; pairid(11b) = gb*8 + p*4 + q
            #pragma unroll
            for (int ra = 0; ra < 2; ra++) {
                const float* P0 = ACC(ra, 0);
                const float* P1 = ACC(ra, 1);
                #pragma unroll
                for (int h = 0; h < 2; h++) {
                    const int g = ra * 2 + h;
                    {
                        float pm = fmaxf(P0[2 * h], P0[2 * h + 1]);
                        unsigned pid = ((unsigned)gb << 3) | lane_q;
                        float pv = __uint_as_float((__float_as_uint(pm) & 0xFFFFF800u) | pid);
                        cs_[g] = fmaxf(cs_[g], fminf(cb_[g], pv));
                        cb_[g] = fmaxf(cb_[g], pv);
                    }
                    {
                        float pm = fmaxf(P1[2 * h], P1[2 * h + 1]);
                        unsigned pid = ((unsigned)gb << 3) | 4u | lane_q;
                        float pv = __uint_as_float((__float_as_uint(pm) & 0xFFFFF800u) | pid);
                        cs_[g] = fmaxf(cs_[g], fminf(cb_[g], pv));
                        cb_[g] = fmaxf(cb_[g], pv);
                    }
                }
            }
        }

        // per-row top-3 pairs: promote chain top-2, quad-lane merge
        #pragma unroll
        for (int g = 0; g < 4; g++) {
            float tv[3];
            tv[0] = cb_[g]; tv[1] = cs_[g]; tv[2] = NEG_INF;
            merge3f_shfl(tv, 1);
            merge3f_shfl(tv, 2);
            if ((l & 3) == 0) {
                const int ra = g >> 1, rh = g & 1;
                const int row = rg * 32 + ra * 16 + rh * 8 + (l >> 2);
                const int ix  = wc * 64 + row;
                s_v0[ix] = tv[0]; s_v1[ix] = tv[1]; s_v2[ix] = tv[2];
            }
        }
        __syncthreads();

        // merge col-groups, emit packed top-3 per row
        if (tid < MT) {
            float tv[3];
            tv[0] = s_v0[tid]; tv[1] = s_v1[tid]; tv[2] = s_v2[tid];
            ins3f(tv, s_v0[64 + tid]);
            ins3f(tv, s_v1[64 + tid]);
            ins3f(tv, s_v2[64 + tid]);
            g_top4[tile * MT + tid] = make_float4(tv[0], tv[1], tv[2], 0.0f);
        }
        __syncthreads();
    }
}

// ===================== kernel B: rescore + outputs + loss partials =====================
__global__ void __launch_bounds__(256)
vq_epi_kernel(float* __restrict__ out, const float* __restrict__ z_e,
              const float* __restrict__ cb, int out_size_i) {
    __shared__ float shred[8];
    const size_t osz = (size_t)out_size_i;
    const int tid = threadIdx.x;
    const int m   = blockIdx.x * 256 + tid;

    float4 tp = g_top4[m];
    float tv[3] = {tp.x, tp.y, tp.z};

    const float4* zr = reinterpret_cast<const float4*>(z_e + (size_t)m * D_DIM);
    float4 zv[16];
    #pragma unroll
    for (int j = 0; j < 16; j++) zv[j] = zr[j];

    float bestv = NEG_INF;
    int   fin   = K_CODES;
    #pragma unroll
    for (int c3 = 0; c3 < 3; c3++) {
        const int col0 = (int)(__float_as_uint(tv[c3]) & 2047u) * 2;
        #pragma unroll
        for (int oi = 0; oi < 2; oi++) {
            const int code = col0 + oi;
            const float4* er = reinterpret_cast<const float4*>(cb + (size_t)code * D_DIM);
            float s = -g_c[code];
            #pragma unroll
            for (int j = 0; j < 16; j++) {
                float4 e = er[j];
                s += zv[j].x * e.x + zv[j].y * e.y + zv[j].z * e.z + zv[j].w * e.w;
            }
            if (s > bestv || (s == bestv && code < fin)) { bestv = s; fin = code; }
        }
    }

    // outputs
    const size_t MD    = (size_t)M_ROWS * D_DIM;
    const size_t base2 = MD + M_ROWS + 2;
    const float4* er = reinterpret_cast<const float4*>(cb + (size_t)fin * D_DIM);
    float4* out4 = reinterpret_cast<float4*>(out);
    float2* out2 = reinterpret_cast<float2*>(out);
    const size_t o1 = (size_t)m * D_DIM;
    const size_t o3 = base2 + (size_t)m * D_DIM;

    float lsum = 0.0f;
    #pragma unroll
    for (int j = 0; j < 16; j++) {
        float4 e = er[j];
        float4 z = zv[j];
        float4 zst;
        zst.x = z.x + (e.x - z.x);
        zst.y = z.y + (e.y - z.y);
        zst.z = z.z + (e.z - z.z);
        zst.w = z.w + (e.w - z.w);
        float d0 = z.x - e.x, d1 = z.y - e.y, d2 = z.z - e.z, d3 = z.w - e.w;
        lsum += d0 * d0 + d1 * d1 + d2 * d2 + d3 * d3;
        if (o1 + (size_t)j * 4 + 4 <= osz) out4[o1 / 4 + j] = zst;
        if (o3 + (size_t)j * 4 + 4 <= osz) {
            out2[o3 / 2 + 2 * j]     = make_float2(e.x, e.y);
            out2[o3 / 2 + 2 * j + 1] = make_float2(e.z, e.w);
        }
    }
    if (MD + (size_t)m < osz) out[MD + (size_t)m] = (float)fin;

    #pragma unroll
    for (int o = 16; o > 0; o >>= 1) lsum += __shfl_down_sync(0xffffffffu, lsum, o);
    if ((tid & 31) == 0) shred[tid >> 5] = lsum;
    __syncthreads();
    if (tid == 0) {
        float t = 0.0f;
        #pragma unroll
        for (int i = 0; i < 8; i++) t += shred[i];
        g_partials[blockIdx.x] = t;
    }
}

// ===================== finalize: vq_loss + perplexity =====================
__global__ void vq_finalize_kernel(const float* __restrict__ ema,
                                   float* __restrict__ out, int out_size_i) {
    __shared__ float red[1024];
    const size_t osz = (size_t)out_size_i;
    const int tid = threadIdx.x;

    float v = (tid < 256) ? g_partials[tid] : 0.0f;
    red[tid] = v;
    for (int o = 512; o > 0; o >>= 1) {
        __syncthreads();
        if (tid < o) red[tid] += red[tid + o];
    }
    __syncthreads();
    const float vq_loss = 0.25f * red[0] / (float)((size_t)M_ROWS * D_DIM);
    __syncthreads();

    float s = 0.0f;
    for (int i = tid; i < K_CODES; i += 1024) s += ema[i] + 1e-10f;
    red[tid] = s;
    for (int o = 512; o > 0; o >>= 1) {
        __syncthreads();
        if (tid < o) red[tid] += red[tid + o];
    }
    __syncthreads();
    const float S = red[0];
    __syncthreads();

    float ent = 0.0f;
    for (int i = tid; i < K_CODES; i += 1024) {
        float p = (ema[i] + 1e-10f) / S;
        ent += p * logf(p);
    }
    red[tid] = ent;
    for (int o = 512; o > 0; o >>= 1) {
        __syncthreads();
        if (tid < o) red[tid] += red[tid + o];
    }
    __syncthreads();

    if (tid == 0) {
        const size_t base = (size_t)M_ROWS * D_DIM + M_ROWS;
        if (base < osz)     out[base]     = vq_loss;
        if (base + 1 < osz) out[base + 1] = expf(-red[0]);
    }
}

extern "C" void kernel_launch(void* const* d_in, const int* in_sizes, int n_in,
                              void* d_out, int out_size) {
    const float* z_e = (const float*)d_in[0];   // (65536, 64) f32
    const float* cb  = (const float*)d_in[1];   // (4096, 64) f32
    const float* ema = (const float*)d_in[2];   // (4096,) f32
    float* out = (float*)d_out;

    cudaFuncSetAttribute(vq_mma_kernel,
                         cudaFuncAttributeMaxDynamicSharedMemorySize, SMEM_DYN);

    vq_prep_c<<<K_CODES / 8, 256>>>(cb);
    vq_prep_Cf<<<1, 1024>>>();
    vq_prep_A<<<M_ROWS / 8, 256>>>(z_e);
    vq_prep_Bf<<<(NCB16 * NSTEP * 32 * 4) / 256, 256>>>(cb);
    vq_mma_kernel<<<GRID_A, CTA_THREADS, SMEM_DYN>>>();
    vq_epi_kernel<<<M_ROWS / 256, 256>>>(out, z_e, cb, out_size);
    vq_finalize_kernel<<<1, 1024>>>(ema, out, out_size);
}